// round 5
// baseline (speedup 1.0000x reference)
#include <cuda_runtime.h>
#include <math.h>

#define Bn 1024
#define Tn 512
#define KK 48
#define NEG (-10000.0f)
#define SSTART 46
#define SSTOP  47
#define BPB 8
#define NTHREADS (BPB * KK)   // 384
#define NBLK (Bn / BPB)       // 128

// Viterbi value history: v ENTERING each step t, per (b, t, s).  ~100 MB scratch.
__device__ float vbuf_g[(size_t)Bn * Tn * KK];

__global__ void __launch_bounds__(NTHREADS, 1)
crf_fused_kernel(const float* __restrict__ feats,
                 const float* __restrict__ trans,
                 const int*   __restrict__ tags,
                 float*       __restrict__ out)
{
    __shared__ __align__(16) float bufE[2][BPB][KK];  // exp(alpha - norm), double buffered
    __shared__ __align__(16) float bufV[2][BPB][KK];  // viterbi v, double buffered
    __shared__ float trM[KK * KK];                    // masked transitions
    __shared__ float normU[2][BPB];                   // normalizer USED for bufE[q]
    __shared__ float normP[2][BPB];                   // published alpha[0] (next normalizer)
    __shared__ float gbuf[BPB][KK];                   // gold partials
    __shared__ int   blast[BPB];                      // best last tag

    const int tid = threadIdx.x;
    const int bl  = tid / KK;
    const int s   = tid % KK;
    const int b   = blockIdx.x * BPB + bl;

    // Masked transition matrix: trans[next,prev]; row START and col STOP -> NEG
    for (int idx = tid; idx < KK * KK; idx += NTHREADS) {
        int n = idx / KK, p = idx % KK;
        float v = trans[idx];
        if (n == SSTART) v = NEG;
        if (p == SSTOP)  v = NEG;
        trM[idx] = v;
    }
    __syncthreads();

    // Per-thread rows in registers
    float Erow[KK], Trow[KK];
#pragma unroll
    for (int i = 0; i < KK; i++) {
        float tv = trM[s * KK + i];
        Trow[i] = tv;
        Erow[i] = __expf(tv);      // exp(-10000) underflows to exactly 0
    }
    const float tstop = trM[SSTOP * KK + s];

    // Gold score partials (strided over t)
    const float* fb = feats + (size_t)b * Tn * KK;
    const int*   tb = tags  + (size_t)b * Tn;
    {
        float gp = 0.0f;
        for (int t = s; t < Tn; t += KK) {
            int tg = tb[t];
            int pv = (t == 0) ? SSTART : tb[t - 1];
            gp += fb[(size_t)t * KK + tg] + trM[tg * KK + pv];
        }
        gbuf[bl][s] = gp;
    }

    // Init (parity 0): alpha_init = NEG except START=0 -> exp:{1,0}; v likewise
    bufE[0][bl][s] = (s == SSTART) ? 1.0f : 0.0f;
    bufV[0][bl][s] = (s == SSTART) ? 0.0f : NEG;
    if (s == 0) { normU[0][bl] = 0.0f; normP[0][bl] = 0.0f; }

    float alpha = 0.0f;
    float v = (s == SSTART) ? 0.0f : NEG;   // ENTRY value for t=0

    const float* fptr = fb + s;
    float* vrow = vbuf_g + (size_t)b * Tn * KK + s;
    float femit = fptr[0];

#pragma unroll 1
    for (int t = 0; t < Tn; t++) {
        __syncthreads();
        const int p = t & 1;
        const float M = normU[p][bl];     // normalizer used for bufE[p]
        const float W = normP[p][bl];     // normalizer for writing bufE[p^1]
        const float emit = femit;
        const float* np = fptr + KK;
        femit = (t < Tn - 1) ? np[0] : 0.0f;   // prefetch next emit
        fptr = np;

        vrow[(size_t)t * KK] = v;          // store ENTRY v for backtrace recompute

        const float4* E4 = (const float4*)&bufE[p][bl][0];   // 12 float4s
        const float4* V4 = (const float4*)&bufV[p][bl][0];

        float ss0 = 0.f, ss1 = 0.f, ss2 = 0.f, ss3 = 0.f;
        float m0 = -INFINITY, m1 = -INFINITY, m2 = -INFINITY, m3 = -INFINITY;
#pragma unroll
        for (int c = 0; c < 12; c++) {
            const float4 e  = E4[c];
            const float4 vv = V4[c];
            ss0 = fmaf(Erow[4 * c + 0], e.x, ss0);
            ss1 = fmaf(Erow[4 * c + 1], e.y, ss1);
            ss2 = fmaf(Erow[4 * c + 2], e.z, ss2);
            ss3 = fmaf(Erow[4 * c + 3], e.w, ss3);
            m0 = fmaxf(m0, vv.x + Trow[4 * c + 0]);
            m1 = fmaxf(m1, vv.y + Trow[4 * c + 1]);
            m2 = fmaxf(m2, vv.z + Trow[4 * c + 2]);
            m3 = fmaxf(m3, vv.w + Trow[4 * c + 3]);
        }
        const float ssum = (ss0 + ss1) + (ss2 + ss3);
        const float best = fmaxf(fmaxf(m0, m1), fmaxf(m2, m3));  // exact set-max

        alpha = emit + M + __logf(ssum);   // log(0) -> -inf for START row: correct
        v     = best + emit;               // bit-identical value to reference

        const int q = p ^ 1;
        bufE[q][bl][s] = __expf(alpha - W);
        bufV[q][bl][s] = v;
        if (s == 0) { normU[q][bl] = W; normP[q][bl] = alpha; }
    }

    __syncthreads();
    // Terminal terms into buffer 0 (loop done; buffers free)
    bufE[0][bl][s] = alpha + tstop;
    bufV[0][bl][s] = v + tstop;
    __syncthreads();

    if (s == 0) {
        float gold = 0.0f;
        for (int i = 0; i < KK; i++) gold += gbuf[bl][i];
        gold += trM[SSTOP * KK + tb[Tn - 1]];

        float mz = -INFINITY;
        for (int i = 0; i < KK; i++) mz = fmaxf(mz, bufE[0][bl][i]);
        float sz = 0.0f;
        for (int i = 0; i < KK; i++) sz += __expf(bufE[0][bl][i] - mz);
        const float logZ = mz + __logf(sz);

        float bv = -INFINITY; int bi = 0;
        for (int i = 0; i < KK; i++) {
            float tv = bufV[0][bl][i];
            if (tv > bv) { bv = tv; bi = i; }   // first-index tie-break
        }
        out[b]      = logZ - gold;   // nll
        out[Bn + b] = bv;            // path_score
        blast[bl]   = bi;
        out[2 * (size_t)Bn + (size_t)b * Tn + (Tn - 1)] = (float)bi;
    }
    __syncthreads();

    // ---- Backtrace: one warp per batch, recompute backpointers from vbuf ----
    const int w = tid >> 5;
    const int lane = tid & 31;
    if (w < BPB) {
        const int bb = blockIdx.x * BPB + w;
        const float* vb = vbuf_g + (size_t)bb * Tn * KK;
        float* pout = out + 2 * (size_t)Bn + (size_t)bb * Tn;
        int cur = blast[w];

        // depth-4 prefetch ring over rows t = 511..508
        float ra[4], rb[4];
#pragma unroll
        for (int k = 0; k < 4; k++) {
            int tt = Tn - 1 - k;
            ra[k] = vb[(size_t)tt * KK + lane];
            rb[k] = (lane < 16) ? vb[(size_t)tt * KK + 32 + lane] : -INFINITY;
        }

        int t = Tn - 1;
#pragma unroll 1
        for (int iter = 0; iter < 128; iter++) {
#pragma unroll
            for (int k = 0; k < 4; k++) {
                if (t >= 1) {
                    // bp(t,cur) = first-argmax_prev( v_entry[t][prev] + trM[cur][prev] )
                    float val = ra[k] + trM[cur * KK + lane];
                    int   idx = lane;
                    if (lane < 16) {
                        float vB = rb[k] + trM[cur * KK + 32 + lane];
                        if (vB > val) { val = vB; idx = lane + 32; }  // tie -> lower idx
                    }
#pragma unroll
                    for (int off = 16; off >= 1; off >>= 1) {
                        float ov = __shfl_xor_sync(0xffffffffu, val, off);
                        int   oi = __shfl_xor_sync(0xffffffffu, idx, off);
                        if (ov > val || (ov == val && oi < idx)) { val = ov; idx = oi; }
                    }
                    cur = idx;
                    if (lane == 0) pout[t - 1] = (float)cur;

                    const int tn = t - 4;            // refill this ring slot
                    if (tn >= 1) {
                        ra[k] = vb[(size_t)tn * KK + lane];
                        if (lane < 16) rb[k] = vb[(size_t)tn * KK + 32 + lane];
                    }
                    t--;
                }
            }
        }
    }
}

extern "C" void kernel_launch(void* const* d_in, const int* in_sizes, int n_in,
                              void* d_out, int out_size)
{
    const float* feats = (const float*)d_in[0];
    const float* trans = (const float*)d_in[1];
    const int*   tags  = (const int*)d_in[2];
    float* out = (float*)d_out;

    crf_fused_kernel<<<NBLK, NTHREADS>>>(feats, trans, tags, out);
}